// round 4
// baseline (speedup 1.0000x reference)
#include <cuda_runtime.h>
#include <math.h>

#define L_SEQ 1024
#define NB    16
#define DH    512
#define MROWS (L_SEQ*NB)
#define NCLS  64
#define CLU   8          // CTAs per cluster (one cluster per batch)

// ---------------- static device scratch (no allocations) ----------------
__device__ __align__(16) float g_bufE[MROWS*DH];   // embedded input
__device__ __align__(16) float g_buf0[MROWS*DH];   // layer0 xs -> layer0 out (in place)
__device__ __align__(16) float g_buf1[MROWS*DH];   // layer1 xs -> layer1 out (in place)
__device__ __align__(16) float g_Wt[DH*DH];        // transposed W_ih[l]

__device__ __forceinline__ float* bufsel(int s) {
    return (s == 0) ? g_bufE : ((s == 1) ? g_buf0 : g_buf1);
}

__device__ __forceinline__ unsigned smem_u32(const void* p) {
    unsigned a;
    asm("{ .reg .u64 t; cvta.to.shared.u64 t, %1; cvt.u32.u64 %0, t; }" : "=r"(a) : "l"(p));
    return a;
}

#define FMA2(acc, a, b) \
    asm volatile("fma.rn.f32x2 %0, %1, %2, %0;" : "+l"(acc) : "l"(a), "l"(b))
#define PACK2(d, x, y) \
    asm("mov.b64 %0, {%1, %2};" : "=l"(d) : "f"(x), "f"(y))
#define UNPACK2(x, y, d) \
    asm("mov.b64 {%0, %1}, %2;" : "=f"(x), "=f"(y) : "l"(d))

// ---------------- embedding gather ----------------
__global__ void embed_kernel(const int* __restrict__ x, const float* __restrict__ emb) {
    int m = blockIdx.x;              // m = t*16 + n
    int t = m >> 4, n = m & 15;
    int tok = x[n * L_SEQ + t];
    float4* dst = (float4*)(g_bufE + (size_t)m * DH);
    const float4* src = (const float4*)(emb + (size_t)tok * DH);
    dst[threadIdx.x] = src[threadIdx.x];
}

// ---------------- transpose 512x512: g_Wt[k][j] = W[j][k] ----------------
__global__ void transpose_kernel(const float* __restrict__ W) {
    __shared__ float tile[32][33];
    int bx = blockIdx.x * 32, by = blockIdx.y * 32;
    int tx = threadIdx.x, ty = threadIdx.y;
    tile[ty][tx] = W[(by + ty) * DH + bx + tx];
    __syncthreads();
    g_Wt[(bx + ty) * DH + by + tx] = tile[tx][ty];
}

// ---------------- SGEMM: C[M,512] = A[M,512] @ g_Wt + b1 + b2 ----------------
__global__ __launch_bounds__(256) void sgemm_bias(int selA, int selC,
                                                  const float* __restrict__ b1,
                                                  const float* __restrict__ b2) {
    const int N = DH, K = DH;
    const float* A = bufsel(selA);
    float* C = bufsel(selC);
    const float* B = g_Wt;

    __shared__ float As[8][128];
    __shared__ float Bs[8][128];

    int tid  = threadIdx.x;
    int crow = blockIdx.y, ccol = blockIdx.x;
    int trow = tid >> 4, tcol = tid & 15;
    int aRow = tid >> 1, aCol = (tid & 1) * 4;
    int bRow = tid >> 5, bCol = (tid & 31) * 4;

    const float* Ab = A + (size_t)crow * 128 * K;
    const float* Bb = B + ccol * 128;

    float acc[8][8];
#pragma unroll
    for (int i = 0; i < 8; i++)
#pragma unroll
        for (int j = 0; j < 8; j++) acc[i][j] = 0.f;

    for (int k0 = 0; k0 < K; k0 += 8) {
        float4 av = *(const float4*)(Ab + (size_t)aRow * K + k0 + aCol);
        As[aCol + 0][aRow] = av.x;
        As[aCol + 1][aRow] = av.y;
        As[aCol + 2][aRow] = av.z;
        As[aCol + 3][aRow] = av.w;
        *(float4*)(&Bs[bRow][bCol]) = *(const float4*)(Bb + (size_t)(k0 + bRow) * N + bCol);
        __syncthreads();
#pragma unroll
        for (int kk = 0; kk < 8; kk++) {
            float rm[8], rn[8];
#pragma unroll
            for (int i = 0; i < 8; i++) rm[i] = As[kk][trow * 8 + i];
#pragma unroll
            for (int j = 0; j < 8; j++) rn[j] = Bs[kk][tcol * 8 + j];
#pragma unroll
            for (int i = 0; i < 8; i++)
#pragma unroll
                for (int j = 0; j < 8; j++) acc[i][j] += rm[i] * rn[j];
        }
        __syncthreads();
    }

    float bias[8];
#pragma unroll
    for (int j = 0; j < 8; j++) {
        int col = ccol * 128 + tcol * 8 + j;
        bias[j] = b1[col] + b2[col];
    }
#pragma unroll
    for (int i = 0; i < 8; i++) {
        int row = crow * 128 + trow * 8 + i;
        float4* cp = (float4*)(C + (size_t)row * N + ccol * 128 + tcol * 8);
        cp[0] = make_float4(acc[i][0] + bias[0], acc[i][1] + bias[1],
                            acc[i][2] + bias[2], acc[i][3] + bias[3]);
        cp[1] = make_float4(acc[i][4] + bias[4], acc[i][5] + bias[5],
                            acc[i][6] + bias[6], acc[i][7] + bias[7]);
    }
}

// ---------------- recurrence: one 8-CTA cluster per batch ----------------
// mbarrier producer/consumer sync (no cluster.sync in the loop).
// CTA rank owns rows [rank*64, +64). Thread = (rowl=tid>>3, seg=tid&7);
// holds Wh[row][seg*64..+63] packed as 32 f32x2 regs. h double-buffered in
// SMEM (replicated per CTA); lane0 of each warp pushes its 4 rows as one
// 16B st.shared::cluster.v4 to each of 8 peers; tids 0..7 do one remote
// mbarrier arrive each; everyone parity-waits.
__global__ void __launch_bounds__(512, 1) __cluster_dims__(CLU, 1, 1)
rec_cluster(int selBuf, const float* __restrict__ Wh) {
    __shared__ __align__(16) float h_s[2][DH];
    __shared__ __align__(8) unsigned long long mbar;

    float* buf = bufsel(selBuf);
    int tid  = threadIdx.x;
    int seg  = tid & 7;
    int rowl = tid >> 3;                 // 0..63
    int lane = tid & 31;
    int wrp  = tid >> 5;                 // 0..15
    unsigned rank;
    asm("mov.u32 %0, %%cluster_ctarank;" : "=r"(rank));
    int n = blockIdx.x >> 3;             // batch
    int r = (int)rank * 64 + rowl;       // global output row 0..511

    // pack weights into f32x2 registers
    unsigned long long w[32];
    {
        const float4* wp = (const float4*)(Wh + (size_t)r * DH + seg * 64);
#pragma unroll
        for (int j = 0; j < 16; j++) {
            float4 v = wp[j];
            PACK2(w[2 * j],     v.x, v.y);
            PACK2(w[2 * j + 1], v.z, v.w);
        }
    }

    unsigned mb    = smem_u32(&mbar);
    unsigned hbase = smem_u32(h_s);
    if (tid == 0)
        asm volatile("mbarrier.init.shared.b64 [%0], %1;" :: "r"(mb), "r"(CLU) : "memory");
    __syncthreads();
    asm volatile("barrier.cluster.arrive.aligned;" ::: "memory");
    asm volatile("barrier.cluster.wait.aligned;" ::: "memory");

    bool wlane = (seg == 0);
    float xs = 0.f;
    if (wlane) xs = __ldg(&buf[((size_t)n << 9) + r]);

    for (int t = 0; t < L_SEQ; t++) {
        float acc = 0.f;
        if (t > 0) {
            unsigned long long a2 = 0ull;
            const ulonglong2* h2 = (const ulonglong2*)&h_s[t & 1][seg * 64];
#pragma unroll
            for (int j = 0; j < 16; j++) {
                ulonglong2 hv = h2[j];
                FMA2(a2, w[2 * j],     hv.x);
                FMA2(a2, w[2 * j + 1], hv.y);
            }
            float lo, hi;
            UNPACK2(lo, hi, a2);
            acc = lo + hi;
        }
        acc += __shfl_xor_sync(0xFFFFFFFFu, acc, 1);
        acc += __shfl_xor_sync(0xFFFFFFFFu, acc, 2);
        acc += __shfl_xor_sync(0xFFFFFFFFu, acc, 4);

        float v = 0.f;
        if (wlane) v = tanhf(xs + acc);
        // gather the warp's 4 row values (rows wrp*4..wrp*4+3 at lanes 0,8,16,24)
        float vx = __shfl_sync(0xFFFFFFFFu, v, 0);
        float vy = __shfl_sync(0xFFFFFFFFu, v, 8);
        float vz = __shfl_sync(0xFFFFFFFFu, v, 16);
        float vw = __shfl_sync(0xFFFFFFFFu, v, 24);
        if (lane == 0) {
            float4 q = make_float4(vx, vy, vz, vw);
            *(float4*)&buf[((size_t)(t * NB + n) << 9) + rank * 64 + wrp * 4] = q;
            unsigned off = hbase + (unsigned)(((((t + 1) & 1) * DH) + rank * 64 + wrp * 4) * 4);
#pragma unroll
            for (int d = 0; d < CLU; d++) {
                asm volatile(
                    "{ .reg .b32 ra; mapa.shared::cluster.u32 ra, %0, %1;\n\t"
                    "st.shared::cluster.v4.b32 [ra], {%2,%3,%4,%5}; }"
                    :: "r"(off), "r"(d),
                       "r"(__float_as_uint(q.x)), "r"(__float_as_uint(q.y)),
                       "r"(__float_as_uint(q.z)), "r"(__float_as_uint(q.w)) : "memory");
            }
        }
        __syncthreads();
        if (tid < CLU) {
            asm volatile("fence.acq_rel.cluster;" ::: "memory");
            asm volatile(
                "{ .reg .b32 ra; mapa.shared::cluster.u32 ra, %0, %1;\n\t"
                "mbarrier.arrive.shared::cluster.b64 _, [ra]; }"
                :: "r"(mb), "r"(tid) : "memory");
        }
        if (wlane && t + 1 < L_SEQ)
            xs = __ldg(&buf[((size_t)((t + 1) * NB + n) << 9) + r]);
        {
            unsigned ph = (unsigned)(t & 1);
            asm volatile(
                "{ .reg .pred P;\n\t"
                "WL_%=:\n\t"
                "mbarrier.try_wait.parity.acquire.cta.shared::cta.b64 P, [%0], %1, 0x989680;\n\t"
                "@P bra.uni WD_%=;\n\t"
                "bra.uni WL_%=;\n\t"
                "WD_%=: }" :: "r"(mb), "r"(ph) : "memory");
        }
        asm volatile("fence.acq_rel.cluster;" ::: "memory");
    }
}

// ---------------- head: attention at eos + decoder ----------------
__global__ __launch_bounds__(256) void head_kernel(const int* __restrict__ eos,
                                                   const float* __restrict__ Wc,
                                                   const float* __restrict__ bc,
                                                   const float* __restrict__ Wd,
                                                   const float* __restrict__ bd,
                                                   float* __restrict__ logit) {
    const float* out = g_buf1;            // [t][n][512]
    int b = blockIdx.x;
    int tid = threadIdx.x, warp = tid >> 5, lane = tid & 31;

    __shared__ __align__(16) float cat[2 * DH];
    __shared__ __align__(16) float sc[L_SEQ];
    __shared__ __align__(16) float dec[DH];
    __shared__ float red[8];
    __shared__ float s_m, s_denom;

    int e = eos[b];
    int se = (e > 0) ? e : L_SEQ;

    for (int d = tid; d < DH; d += 256) cat[DH + d] = out[(size_t)(e * NB + b) * DH + d];
    __syncthreads();

    if (e > 0) {
        const float4* qv = (const float4*)(cat + DH);
        for (int s = warp; s < se; s += 8) {
            const float4* row = (const float4*)(out + (size_t)(s * NB + b) * DH);
            float p = 0.f;
            for (int j = lane; j < 128; j += 32) {
                float4 r4 = row[j], q4 = qv[j];
                p += r4.x * q4.x + r4.y * q4.y + r4.z * q4.z + r4.w * q4.w;
            }
#pragma unroll
            for (int o = 16; o > 0; o >>= 1) p += __shfl_xor_sync(0xFFFFFFFFu, p, o);
            if (lane == 0) sc[s] = p;
        }
        __syncthreads();
        float m = -1e30f;
        for (int s = tid; s < se; s += 256) m = fmaxf(m, sc[s]);
#pragma unroll
        for (int o = 16; o > 0; o >>= 1) m = fmaxf(m, __shfl_xor_sync(0xFFFFFFFFu, m, o));
        if (lane == 0) red[warp] = m;
        __syncthreads();
        if (tid == 0) {
            float mm = red[0];
            for (int i = 1; i < 8; i++) mm = fmaxf(mm, red[i]);
            s_m = mm;
        }
        __syncthreads();
        float mm = s_m, sum = 0.f;
        for (int s = tid; s < se; s += 256) {
            float v = expf(sc[s] - mm);
            sc[s] = v;
            sum += v;
        }
#pragma unroll
        for (int o = 16; o > 0; o >>= 1) sum += __shfl_xor_sync(0xFFFFFFFFu, sum, o);
        if (lane == 0) red[warp] = sum;
        __syncthreads();
        if (tid == 0) {
            float ss = 0.f;
            for (int i = 0; i < 8; i++) ss += red[i];
            s_denom = ss;
        }
        __syncthreads();
    }

    float inv = (e > 0) ? (1.f / s_denom) : (1.f / (float)L_SEQ);
    float az0 = 0.f, az1 = 0.f;
    for (int s = 0; s < se; s++) {
        float a = (e > 0) ? sc[s] * inv : inv;
        az0 += a * out[(size_t)(s * NB + b) * DH + tid];
        az1 += a * out[(size_t)(s * NB + b) * DH + tid + 256];
    }
    cat[tid] = az0;
    cat[tid + 256] = az1;
    __syncthreads();

    const float4* c4 = (const float4*)cat;
    for (int r = warp; r < DH; r += 8) {
        const float4* wr = (const float4*)(Wc + (size_t)r * (2 * DH));
        float p = 0.f;
        for (int j = lane; j < 256; j += 32) {
            float4 a4 = c4[j], w4 = wr[j];
            p += a4.x * w4.x + a4.y * w4.y + a4.z * w4.z + a4.w * w4.w;
        }
#pragma unroll
        for (int o = 16; o > 0; o >>= 1) p += __shfl_xor_sync(0xFFFFFFFFu, p, o);
        if (lane == 0) dec[r] = p + bc[r];
    }
    __syncthreads();

    const float4* d4 = (const float4*)dec;
    for (int c = warp; c < NCLS; c += 8) {
        const float4* wd = (const float4*)(Wd + (size_t)c * DH);
        float p = 0.f;
        for (int j = lane; j < 128; j += 32) {
            float4 a4 = d4[j], w4 = wd[j];
            p += a4.x * w4.x + a4.y * w4.y + a4.z * w4.z + a4.w * w4.w;
        }
#pragma unroll
        for (int o = 16; o > 0; o >>= 1) p += __shfl_xor_sync(0xFFFFFFFFu, p, o);
        if (lane == 0) logit[b * NCLS + c] = p + bd[c];
    }
}

// ---------------- launch ----------------
extern "C" void kernel_launch(void* const* d_in, const int* in_sizes, int n_in,
                              void* d_out, int out_size) {
    const int*   x    = (const int*)d_in[0];
    const int*   eos  = (const int*)d_in[1];
    const float* emb  = (const float*)d_in[2];
    const float* W_ih = (const float*)d_in[3];
    const float* W_hh = (const float*)d_in[4];
    const float* b_ih = (const float*)d_in[5];
    const float* b_hh = (const float*)d_in[6];
    const float* Wc   = (const float*)d_in[7];
    const float* bc   = (const float*)d_in[8];
    const float* Wd   = (const float*)d_in[9];
    const float* bd   = (const float*)d_in[10];
    float* logit = (float*)d_out;

    dim3 tb(32, 32), tg(16, 16);
    dim3 gg(DH / 128, MROWS / 128);

    embed_kernel<<<MROWS, 128>>>(x, emb);

    transpose_kernel<<<tg, tb>>>(W_ih);
    sgemm_bias<<<gg, 256>>>(0, 1, b_ih, b_hh);            // bufE -> buf0
    rec_cluster<<<NB * CLU, 512>>>(1, W_hh);              // layer 0

    transpose_kernel<<<tg, tb>>>(W_ih + DH * DH);
    sgemm_bias<<<gg, 256>>>(1, 2, b_ih + DH, b_hh + DH);  // buf0 -> buf1
    rec_cluster<<<NB * CLU, 512>>>(2, W_hh + DH * DH);    // layer 1

    head_kernel<<<NB, 256>>>(eos, Wc, bc, Wd, bd, logit);
}

// round 12
// speedup vs baseline: 4.5478x; 4.5478x over previous
#include <cuda_runtime.h>
#include <math.h>

#define L_SEQ 1024
#define NB    16
#define DH    512
#define MROWS (L_SEQ*NB)
#define NCLS  64

// ---------------- static device scratch (no allocations) ----------------
__device__ __align__(16) float g_bufE[MROWS*DH];   // embedded input
__device__ __align__(16) float g_buf0[MROWS*DH];   // layer0 xs
__device__ __align__(16) float g_buf1[MROWS*DH];   // layer1 xs
__device__ __align__(16) float g_hist0[MROWS*DH];  // layer0 out history
__device__ __align__(16) float g_hist1[MROWS*DH];  // layer1 out history
__device__ __align__(16) float g_Wt[DH*DH];        // transposed W_ih[l]
__device__ unsigned g_flag[2][NB][8][32];          // [layer][batch][chunk], 128B padded

__device__ __forceinline__ float* bufsel(int s) {
    switch (s) {
        case 0: return g_bufE;
        case 1: return g_buf0;
        case 2: return g_buf1;
        case 3: return g_hist0;
        default: return g_hist1;
    }
}

#define FMA2(acc, a, b) \
    asm volatile("fma.rn.f32x2 %0, %1, %2, %0;" : "+l"(acc) : "l"(a), "l"(b))
#define ADD2(d, a, b) \
    asm("add.rn.f32x2 %0, %1, %2;" : "=l"(d) : "l"(a), "l"(b))
#define PACK2(d, x, y) \
    asm("mov.b64 %0, {%1, %2};" : "=l"(d) : "f"(x), "f"(y))
#define UNPACK2(x, y, d) \
    asm("mov.b64 {%0, %1}, %2;" : "=f"(x), "=f"(y) : "l"(d))

// ---------------- reset flags (every launch -> deterministic replays) ----------------
__global__ void reset_kernel() {
    ((unsigned*)g_flag)[blockIdx.x * blockDim.x + threadIdx.x] = 0u;
}

// ---------------- embedding gather ----------------
__global__ void embed_kernel(const int* __restrict__ x, const float* __restrict__ emb) {
    int m = blockIdx.x;              // m = t*16 + n
    int t = m >> 4, n = m & 15;
    int tok = x[n * L_SEQ + t];
    float4* dst = (float4*)(g_bufE + (size_t)m * DH);
    const float4* src = (const float4*)(emb + (size_t)tok * DH);
    dst[threadIdx.x] = src[threadIdx.x];
}

// ---------------- transpose 512x512: g_Wt[k][j] = W[j][k] ----------------
__global__ void transpose_kernel(const float* __restrict__ W) {
    __shared__ float tile[32][33];
    int bx = blockIdx.x * 32, by = blockIdx.y * 32;
    int tx = threadIdx.x, ty = threadIdx.y;
    tile[ty][tx] = W[(by + ty) * DH + bx + tx];
    __syncthreads();
    g_Wt[(bx + ty) * DH + by + tx] = tile[tx][ty];
}

// ---------------- SGEMM: C[M,512] = A[M,512] @ g_Wt + b1 + b2 ----------------
__global__ __launch_bounds__(256) void sgemm_bias(int selA, int selC,
                                                  const float* __restrict__ b1,
                                                  const float* __restrict__ b2) {
    const int N = DH, K = DH;
    const float* A = bufsel(selA);
    float* C = bufsel(selC);
    const float* B = g_Wt;

    __shared__ float As[8][128];
    __shared__ float Bs[8][128];

    int tid  = threadIdx.x;
    int crow = blockIdx.y, ccol = blockIdx.x;
    int trow = tid >> 4, tcol = tid & 15;
    int aRow = tid >> 1, aCol = (tid & 1) * 4;
    int bRow = tid >> 5, bCol = (tid & 31) * 4;

    const float* Ab = A + (size_t)crow * 128 * K;
    const float* Bb = B + ccol * 128;

    float acc[8][8];
#pragma unroll
    for (int i = 0; i < 8; i++)
#pragma unroll
        for (int j = 0; j < 8; j++) acc[i][j] = 0.f;

    for (int k0 = 0; k0 < K; k0 += 8) {
        float4 av = *(const float4*)(Ab + (size_t)aRow * K + k0 + aCol);
        As[aCol + 0][aRow] = av.x;
        As[aCol + 1][aRow] = av.y;
        As[aCol + 2][aRow] = av.z;
        As[aCol + 3][aRow] = av.w;
        *(float4*)(&Bs[bRow][bCol]) = *(const float4*)(Bb + (size_t)(k0 + bRow) * N + bCol);
        __syncthreads();
#pragma unroll
        for (int kk = 0; kk < 8; kk++) {
            float rm[8], rn[8];
#pragma unroll
            for (int i = 0; i < 8; i++) rm[i] = As[kk][trow * 8 + i];
#pragma unroll
            for (int j = 0; j < 8; j++) rn[j] = Bs[kk][tcol * 8 + j];
#pragma unroll
            for (int i = 0; i < 8; i++)
#pragma unroll
                for (int j = 0; j < 8; j++) acc[i][j] += rm[i] * rn[j];
        }
        __syncthreads();
    }

    float bias[8];
#pragma unroll
    for (int j = 0; j < 8; j++) {
        int col = ccol * 128 + tcol * 8 + j;
        bias[j] = b1[col] + b2[col];
    }
#pragma unroll
    for (int i = 0; i < 8; i++) {
        int row = crow * 128 + trow * 8 + i;
        float4* cp = (float4*)(C + (size_t)row * N + ccol * 128 + tcol * 8);
        cp[0] = make_float4(acc[i][0] + bias[0], acc[i][1] + bias[1],
                            acc[i][2] + bias[2], acc[i][3] + bias[3]);
        cp[1] = make_float4(acc[i][4] + bias[4], acc[i][5] + bias[5],
                            acc[i][6] + bias[6], acc[i][7] + bias[7]);
    }
}

// ---------------- recurrence: per-batch flag sync, 8 CTAs per batch ----------------
// grid = 128 CTAs: CTA = (batch n = blockIdx&15, chunk c = blockIdx>>4) owning
// rows [c*64, c*64+64). Thread = (rowl = tid>>3, seg = tid&7), weights for
// cols seg*64..+63 in 32 f32x2 regs. Per step: 8 threads acquire-poll the 8
// per-chunk flags of batch n; 128 threads stage hist[t-1][n] into padded SMEM;
// all FMA + 3-shuffle reduce; writer lanes tanh + st.cg to hist[t][n]; bar;
// tid0 release-stores flag = t+1.
__global__ void __launch_bounds__(512, 1)
rec_flag(int selXs, int selHist, const float* __restrict__ Wh, int layer) {
    __shared__ __align__(16) float h_s[544];   // 512 + 4-float pad per 64

    const float* xsbuf = bufsel(selXs);
    float* hist = bufsel(selHist);
    int tid  = threadIdx.x;
    int n    = blockIdx.x & 15;
    int c    = blockIdx.x >> 4;
    int lane = tid & 31;
    int rowl = tid >> 3;                 // 0..63
    int seg  = tid & 7;                  // 0..7
    int r    = c * 64 + rowl;            // global row

    // pack weights: Wh[r][seg*64 .. +63] -> 32 f32x2
    unsigned long long w[32];
    {
        const float* wr = Wh + (size_t)r * DH + seg * 64;
#pragma unroll
        for (int j = 0; j < 32; j++) PACK2(w[j], wr[2 * j], wr[2 * j + 1]);
    }

    unsigned* myflag = &g_flag[layer][n][c][0];
    bool wl = ((lane & 7) == 0);         // writer lanes 0,8,16,24
    float xs = 0.f;
    if (wl) xs = __ldg(&xsbuf[((size_t)n << 9) + r]);

    for (int t = 0; t < L_SEQ; t++) {
        if (t > 0) {
            if (tid < 8) {
                const unsigned* fp = &g_flag[layer][n][tid][0];
                unsigned v;
                do {
                    asm volatile("ld.acquire.gpu.global.u32 %0, [%1];"
                                 : "=r"(v) : "l"(fp) : "memory");
                } while (v < (unsigned)t);
            }
            __syncthreads();
            if (tid < 128) {             // stage h[t-1][n] -> smem (padded)
                const float* hp = hist + (((size_t)(t - 1) * NB + n) << 9) + tid * 4;
                float4 hv;
                asm volatile("ld.global.cg.v4.f32 {%0,%1,%2,%3}, [%4];"
                             : "=f"(hv.x), "=f"(hv.y), "=f"(hv.z), "=f"(hv.w)
                             : "l"(hp) : "memory");
                int cidx = tid * 4;
                *(float4*)&h_s[cidx + ((cidx >> 6) << 2)] = hv;
            }
            __syncthreads();
        }

        float acc = 0.f;
        if (t > 0) {
            const float* hb = &h_s[seg * 68];
            unsigned long long A0 = 0ull, A1 = 0ull;
#pragma unroll
            for (int m = 0; m < 16; m += 2) {
                ulonglong2 p0 = *(const ulonglong2*)(hb + 4 * m);
                ulonglong2 p1 = *(const ulonglong2*)(hb + 4 * m + 4);
                FMA2(A0, w[2 * m],     p0.x);
                FMA2(A1, w[2 * m + 1], p0.y);
                FMA2(A0, w[2 * m + 2], p1.x);
                FMA2(A1, w[2 * m + 3], p1.y);
            }
            unsigned long long S;
            ADD2(S, A0, A1);
            float lo, hi;
            UNPACK2(lo, hi, S);
            acc = lo + hi;
        }
        // reduce 8 segments (lanes l, l^1, l^2, l^4 share a row)
        acc += __shfl_xor_sync(0xFFFFFFFFu, acc, 1);
        acc += __shfl_xor_sync(0xFFFFFFFFu, acc, 2);
        acc += __shfl_xor_sync(0xFFFFFFFFu, acc, 4);

        if (wl) {
            float v = tanhf(xs + acc);
            __stcg(&hist[((size_t)(t * NB + n) << 9) + r], v);
        }
        __syncthreads();
        if (tid == 0)
            asm volatile("st.release.gpu.global.u32 [%0], %1;"
                         :: "l"(myflag), "r"((unsigned)(t + 1)) : "memory");
        if (wl && t + 1 < L_SEQ)
            xs = __ldg(&xsbuf[(((size_t)(t + 1) * NB + n) << 9) + r]);
    }
}

// ---------------- head: attention at eos + decoder ----------------
__global__ __launch_bounds__(256) void head_kernel(const int* __restrict__ eos,
                                                   const float* __restrict__ Wc,
                                                   const float* __restrict__ bc,
                                                   const float* __restrict__ Wd,
                                                   const float* __restrict__ bd,
                                                   float* __restrict__ logit) {
    const float* out = g_hist1;           // [t][n][512]
    int b = blockIdx.x;
    int tid = threadIdx.x, warp = tid >> 5, lane = tid & 31;

    __shared__ __align__(16) float cat[2 * DH];
    __shared__ __align__(16) float sc[L_SEQ];
    __shared__ __align__(16) float dec[DH];
    __shared__ float red[8];
    __shared__ float s_m, s_denom;

    int e = eos[b];
    int se = (e > 0) ? e : L_SEQ;

    for (int d = tid; d < DH; d += 256) cat[DH + d] = out[(size_t)(e * NB + b) * DH + d];
    __syncthreads();

    if (e > 0) {
        const float4* qv = (const float4*)(cat + DH);
        for (int s = warp; s < se; s += 8) {
            const float4* row = (const float4*)(out + (size_t)(s * NB + b) * DH);
            float p = 0.f;
            for (int j = lane; j < 128; j += 32) {
                float4 r4 = row[j], q4 = qv[j];
                p += r4.x * q4.x + r4.y * q4.y + r4.z * q4.z + r4.w * q4.w;
            }
#pragma unroll
            for (int o = 16; o > 0; o >>= 1) p += __shfl_xor_sync(0xFFFFFFFFu, p, o);
            if (lane == 0) sc[s] = p;
        }
        __syncthreads();
        float m = -1e30f;
        for (int s = tid; s < se; s += 256) m = fmaxf(m, sc[s]);
#pragma unroll
        for (int o = 16; o > 0; o >>= 1) m = fmaxf(m, __shfl_xor_sync(0xFFFFFFFFu, m, o));
        if (lane == 0) red[warp] = m;
        __syncthreads();
        if (tid == 0) {
            float mm = red[0];
            for (int i = 1; i < 8; i++) mm = fmaxf(mm, red[i]);
            s_m = mm;
        }
        __syncthreads();
        float mm = s_m, sum = 0.f;
        for (int s = tid; s < se; s += 256) {
            float v = expf(sc[s] - mm);
            sc[s] = v;
            sum += v;
        }
#pragma unroll
        for (int o = 16; o > 0; o >>= 1) sum += __shfl_xor_sync(0xFFFFFFFFu, sum, o);
        if (lane == 0) red[warp] = sum;
        __syncthreads();
        if (tid == 0) {
            float ss = 0.f;
            for (int i = 0; i < 8; i++) ss += red[i];
            s_denom = ss;
        }
        __syncthreads();
    }

    float inv = (e > 0) ? (1.f / s_denom) : (1.f / (float)L_SEQ);
    float az0 = 0.f, az1 = 0.f;
    for (int s = 0; s < se; s++) {
        float a = (e > 0) ? sc[s] * inv : inv;
        az0 += a * out[(size_t)(s * NB + b) * DH + tid];
        az1 += a * out[(size_t)(s * NB + b) * DH + tid + 256];
    }
    cat[tid] = az0;
    cat[tid + 256] = az1;
    __syncthreads();

    const float4* c4 = (const float4*)cat;
    for (int r = warp; r < DH; r += 8) {
        const float4* wr = (const float4*)(Wc + (size_t)r * (2 * DH));
        float p = 0.f;
        for (int j = lane; j < 256; j += 32) {
            float4 a4 = c4[j], w4 = wr[j];
            p += a4.x * w4.x + a4.y * w4.y + a4.z * w4.z + a4.w * w4.w;
        }
#pragma unroll
        for (int o = 16; o > 0; o >>= 1) p += __shfl_xor_sync(0xFFFFFFFFu, p, o);
        if (lane == 0) dec[r] = p + bc[r];
    }
    __syncthreads();

    const float4* d4 = (const float4*)dec;
    for (int cc = warp; cc < NCLS; cc += 8) {
        const float4* wd = (const float4*)(Wd + (size_t)cc * DH);
        float p = 0.f;
        for (int j = lane; j < 128; j += 32) {
            float4 a4 = d4[j], w4 = wd[j];
            p += a4.x * w4.x + a4.y * w4.y + a4.z * w4.z + a4.w * w4.w;
        }
#pragma unroll
        for (int o = 16; o > 0; o >>= 1) p += __shfl_xor_sync(0xFFFFFFFFu, p, o);
        if (lane == 0) logit[b * NCLS + cc] = p + bd[cc];
    }
}

// ---------------- launch ----------------
extern "C" void kernel_launch(void* const* d_in, const int* in_sizes, int n_in,
                              void* d_out, int out_size) {
    const int*   x    = (const int*)d_in[0];
    const int*   eos  = (const int*)d_in[1];
    const float* emb  = (const float*)d_in[2];
    const float* W_ih = (const float*)d_in[3];
    const float* W_hh = (const float*)d_in[4];
    const float* b_ih = (const float*)d_in[5];
    const float* b_hh = (const float*)d_in[6];
    const float* Wc   = (const float*)d_in[7];
    const float* bc   = (const float*)d_in[8];
    const float* Wd   = (const float*)d_in[9];
    const float* bd   = (const float*)d_in[10];
    float* logit = (float*)d_out;

    dim3 tb(32, 32), tg(16, 16);
    dim3 gg(DH / 128, MROWS / 128);

    reset_kernel<<<8, 1024>>>();                          // zero all flags
    embed_kernel<<<MROWS, 128>>>(x, emb);

    transpose_kernel<<<tg, tb>>>(W_ih);
    sgemm_bias<<<gg, 256>>>(0, 1, b_ih, b_hh);            // bufE -> buf0
    rec_flag<<<128, 512>>>(1, 3, W_hh, 0);                // buf0 -> hist0

    transpose_kernel<<<tg, tb>>>(W_ih + DH * DH);
    sgemm_bias<<<gg, 256>>>(3, 2, b_ih + DH, b_hh + DH);  // hist0 -> buf1
    rec_flag<<<128, 512>>>(2, 4, W_hh + DH * DH, 1);      // buf1 -> hist1

    head_kernel<<<NB, 256>>>(eos, Wc, bc, Wd, bd, logit);
}